// round 4
// baseline (speedup 1.0000x reference)
#include <cuda_runtime.h>
#include <math.h>

#define NP 262144
#define NR_OI 500
#define SUMH 224
#define SUMW 221
#define SCAT_BLOCKS 512
#define SCAT_THREADS 256
#define CHUNK (NP / SCAT_BLOCKS)   // 512
#define LOG2E 1.4426950408889634f

// ---------------- device scratch (no allocations allowed) ----------------
__device__ int   g_counts[NR_OI];
__device__ int   g_offsets[NR_OI + 1];
__device__ int   g_cursor[NR_OI];
__device__ int   g_perm[NP];
__device__ float g_lc[NR_OI][SUMH];     // LOG2E*emb + log2(cw)   (-inf at edges)
__device__ float g_lemb[NR_OI][SUMH];   // LOG2E*emb
__device__ float g_cw[NR_OI][SUMH];     // w[k-1] + w[k]
__device__ float g_w[NR_OI][SUMH];      // softmax widths (pad 0)
__device__ float g_binloc[NR_OI][SUMH]; // bin locations

__device__ __forceinline__ float ex2f(float a) {
    float r;
    asm("ex2.approx.ftz.f32 %0, %1;" : "=f"(r) : "f"(a));
    return r;
}

// ---------------- grouping pre-pass ----------------
__global__ void k_zero() {
    int t = blockIdx.x * blockDim.x + threadIdx.x;
    if (t < NR_OI) g_counts[t] = 0;
}

__global__ void __launch_bounds__(SCAT_THREADS)
k_hist(const int* __restrict__ lrix) {
    __shared__ int sc[NR_OI];
    for (int t = threadIdx.x; t < NR_OI; t += blockDim.x) sc[t] = 0;
    __syncthreads();
    int base = blockIdx.x * CHUNK;
    for (int j = threadIdx.x; j < CHUNK; j += blockDim.x)
        atomicAdd(&sc[lrix[base + j]], 1);
    __syncthreads();
    for (int t = threadIdx.x; t < NR_OI; t += blockDim.x) {
        int c = sc[t];
        if (c) atomicAdd(&g_counts[t], c);
    }
}

__global__ void k_scan() {
    __shared__ int s[512];
    int t = threadIdx.x;
    int v = (t < NR_OI) ? g_counts[t] : 0;
    s[t] = v;
    __syncthreads();
    for (int o = 1; o < 512; o <<= 1) {
        int a = (t >= o) ? s[t - o] : 0;
        __syncthreads();
        s[t] += a;
        __syncthreads();
    }
    if (t < NR_OI) {
        int ex = s[t] - v;
        g_offsets[t] = ex;
        g_cursor[t] = ex;
    }
    if (t == NR_OI - 1) g_offsets[NR_OI] = s[t];
}

__global__ void __launch_bounds__(SCAT_THREADS)
k_scatter(const int* __restrict__ lrix) {
    __shared__ int sc[NR_OI];
    __shared__ int sbase[NR_OI];
    for (int t = threadIdx.x; t < NR_OI; t += blockDim.x) sc[t] = 0;
    __syncthreads();
    int base = blockIdx.x * CHUNK;
    for (int j = threadIdx.x; j < CHUNK; j += blockDim.x)
        atomicAdd(&sc[lrix[base + j]], 1);
    __syncthreads();
    for (int t = threadIdx.x; t < NR_OI; t += blockDim.x) {
        int c = sc[t];
        sbase[t] = c ? atomicAdd(&g_cursor[t], c) : 0;
        sc[t] = 0;
    }
    __syncthreads();
    for (int j = threadIdx.x; j < CHUNK; j += blockDim.x) {
        int i = base + j;
        int r = lrix[i];
        int rank = atomicAdd(&sc[r], 1);
        g_perm[sbase[r] + rank] = i;
    }
}

// ---------------- per-region table prep ----------------
__device__ __forceinline__ float warp_max(float v) {
#pragma unroll
    for (int o = 16; o; o >>= 1) v = fmaxf(v, __shfl_xor_sync(0xffffffffu, v, o));
    return v;
}
__device__ __forceinline__ float warp_sum(float v) {
#pragma unroll
    for (int o = 16; o; o >>= 1) v += __shfl_xor_sync(0xffffffffu, v, o);
    return v;
}

template <int N, int OH, int OW>
__device__ __forceinline__ void prep_level(int r, int rid,
                                           const float* __restrict__ hemb,
                                           const float* __restrict__ wemb,
                                           float* sw) {
    const int M = N - 1;
    int lane = threadIdx.x;

    float vals[4];
    float mx = -1e30f;
#pragma unroll
    for (int j = 0; j < 4; j++) {
        int k = lane + 32 * j;
        vals[j] = (k < M) ? wemb[(size_t)rid * SUMW + OW + k] : -1e30f;
        mx = fmaxf(mx, vals[j]);
    }
    mx = warp_max(mx);

    float es[4];
    float sum = 0.f;
#pragma unroll
    for (int j = 0; j < 4; j++) {
        int k = lane + 32 * j;
        es[j] = (k < M) ? __expf(vals[j] - mx) : 0.f;
        sum += es[j];
    }
    sum = warp_sum(sum);
    float inv = 1.f / sum;

#pragma unroll
    for (int j = 0; j < 4; j++) {
        int k = lane + 32 * j;
        if (k < M) sw[k] = es[j] * inv;
    }
    __syncwarp();

#pragma unroll
    for (int j = 0; j < 4; j++) {
        int k = lane + 32 * j;
        if (k < N) {
            float wk = (k < M) ? sw[k] : 0.f;
            float wkm1 = (k > 0) ? sw[k - 1] : 0.f;
            float cw = wk + wkm1;
            float le = LOG2E * hemb[(size_t)rid * SUMH + OH + k];
            g_w[r][OH + k] = wk;
            g_cw[r][OH + k] = cw;
            g_lemb[r][OH + k] = le;
            g_lc[r][OH + k] = (cw > 0.f) ? (le + __log2f(cw)) : -INFINITY;
        }
    }

    if (lane == 0) {
        float c = 0.f;
        g_binloc[r][OH] = 0.f;
        for (int k = 1; k < N; k++) {
            c += sw[k - 1];
            g_binloc[r][OH + k] = (k == N - 1) ? 1.f : c;
        }
    }
    __syncwarp();
}

__global__ void k_prep(const int* __restrict__ roi,
                       const float* __restrict__ hemb,
                       const float* __restrict__ wemb) {
    __shared__ float sw[128];
    int r = blockIdx.x;
    int rid = roi[r];
    prep_level<128, 0, 0>(r, rid, hemb, wemb, sw);
    prep_level<64, 128, 127>(r, rid, hemb, wemb, sw);
    prep_level<32, 192, 190>(r, rid, hemb, wemb, sw);
}

// ---------------- main per-point kernel ----------------
// 8 lanes per point, 4 points per warp. Phase 1: all loads + exp (xv-indep).
// Phase 2: per-level search + masked partial + epilogue (xv-dependent chain).

template <int N, int OFF, int STEPS, int NT>
__device__ __forceinline__ void level_finish(float& xv, float& ld, int g,
                                             const float* t, float total,
                                             const float* __restrict__ drow,
                                             const float* __restrict__ sLE,
                                             const float* __restrict__ sCW,
                                             const float* __restrict__ sW,
                                             const float* __restrict__ sB) {
    const float* B = sB + OFF;

    int pos = 0;
#pragma unroll
    for (int s = 0; s < STEPS; s++) {
        int step = N >> (s + 1);
        pos += (B[pos + step] < xv) ? step : 0;
    }
    int bin = pos > N - 2 ? N - 2 : pos;

    float partial = 0.f;
#pragma unroll
    for (int m = 0; m < NT; m++) {
        int k = g * 4 + (m >> 2) * 32 + (m & 3);
        partial += (k < bin) ? t[m] : 0.f;
    }
#pragma unroll
    for (int o = 4; o; o >>= 1)
        partial += __shfl_xor_sync(0xffffffffu, partial, o);

    float hl = ex2f(fmaf(__ldg(&drow[OFF + bin]), LOG2E, sLE[OFF + bin]));
    float hr = ex2f(fmaf(__ldg(&drow[OFF + bin + 1]), LOG2E, sLE[OFF + bin + 1]));
    float wb = sW[OFF + bin];
    float wbm1 = sCW[OFF + bin] - wb;
    partial = fmaf(hl, wbm1, partial);

    float inv_t = __fdividef(1.f, total);
    float Hl = 2.f * hl * inv_t;
    float Hr = 2.f * hr * inv_t;
    float incdf = partial * inv_t;
    float alpha = (xv - B[bin]) * __fdividef(1.f, wb);
    float dh = Hr - Hl;
    xv = (0.5f * dh * alpha + Hl) * (wb * alpha) + incdf;
    ld += __logf(fmaf(alpha, dh, Hl));
}

__global__ void __launch_bounds__(128)
k_main(const float* __restrict__ x,
       const float* __restrict__ delta,
       float* __restrict__ out) {
    __shared__ float sLC[SUMH];
    __shared__ float sLE[SUMH];
    __shared__ float sCW[SUMH];
    __shared__ float sW[SUMH];
    __shared__ float sB[SUMH];

    int r = blockIdx.x;
    for (int i = threadIdx.x; i < SUMH; i += blockDim.x) {
        sLC[i] = g_lc[r][i];
        sLE[i] = g_lemb[r][i];
        sCW[i] = g_cw[r][i];
        sW[i] = g_w[r][i];
        sB[i] = g_binloc[r][i];
    }
    __syncthreads();

    int g = threadIdx.x & 7;
    int grpInBlock = threadIdx.x >> 3;
    int beg = g_offsets[r];
    int end = g_offsets[r + 1];
    int stride = gridDim.y * 16;

    for (int j = beg + blockIdx.y * 16 + grpInBlock; j < end; j += stride) {
        int p = g_perm[j];
        float xv = __ldg(&x[p]);
        float ld = 0.f;
        const float* drow = delta + (size_t)p * SUMH;
        const float4* d4 = reinterpret_cast<const float4*>(drow);

        // ---- phase 1: all delta loads in flight, then all exp ----
        float4 dv[7];
#pragma unroll
        for (int i = 0; i < 4; i++) dv[i] = __ldg(&d4[g + 8 * i]);       // level1
#pragma unroll
        for (int i = 0; i < 2; i++) dv[4 + i] = __ldg(&d4[32 + g + 8 * i]); // level2
        dv[6] = __ldg(&d4[48 + g]);                                      // level3

        float t1[16], t2[8], t3[4];
        float tot1 = 0.f, tot2 = 0.f, tot3 = 0.f;
#pragma unroll
        for (int i = 0; i < 4; i++) {
            float dd[4] = {dv[i].x, dv[i].y, dv[i].z, dv[i].w};
#pragma unroll
            for (int jj = 0; jj < 4; jj++) {
                int k = g * 4 + i * 32 + jj;
                float t = ex2f(fmaf(dd[jj], LOG2E, sLC[k]));
                t1[i * 4 + jj] = t;
                tot1 += t;
            }
        }
#pragma unroll
        for (int i = 0; i < 2; i++) {
            float dd[4] = {dv[4 + i].x, dv[4 + i].y, dv[4 + i].z, dv[4 + i].w};
#pragma unroll
            for (int jj = 0; jj < 4; jj++) {
                int k = g * 4 + i * 32 + jj;
                float t = ex2f(fmaf(dd[jj], LOG2E, sLC[128 + k]));
                t2[i * 4 + jj] = t;
                tot2 += t;
            }
        }
        {
            float dd[4] = {dv[6].x, dv[6].y, dv[6].z, dv[6].w};
#pragma unroll
            for (int jj = 0; jj < 4; jj++) {
                int k = g * 4 + jj;
                float t = ex2f(fmaf(dd[jj], LOG2E, sLC[192 + k]));
                t3[jj] = t;
                tot3 += t;
            }
        }
#pragma unroll
        for (int o = 4; o; o >>= 1) {
            tot1 += __shfl_xor_sync(0xffffffffu, tot1, o);
            tot2 += __shfl_xor_sync(0xffffffffu, tot2, o);
            tot3 += __shfl_xor_sync(0xffffffffu, tot3, o);
        }

        // ---- phase 2: dependent per-level finish ----
        level_finish<128, 0, 7, 16>(xv, ld, g, t1, tot1, drow, sLE, sCW, sW, sB);
        level_finish<64, 128, 6, 8>(xv, ld, g, t2, tot2, drow, sLE, sCW, sW, sB);
        level_finish<32, 192, 5, 4>(xv, ld, g, t3, tot3, drow, sLE, sCW, sW, sB);

        if (g == 0) {
            out[p] = xv;
            out[NP + p] = ld;
        }
    }
}

// ---------------- launch ----------------
extern "C" void kernel_launch(void* const* d_in, const int* in_sizes, int n_in,
                              void* d_out, int out_size) {
    const float* x     = (const float*)d_in[0];
    const int*   roi   = (const int*)d_in[1];
    const int*   lrix  = (const int*)d_in[2];
    const float* delta = (const float*)d_in[3];
    const float* hemb  = (const float*)d_in[4];
    const float* wemb  = (const float*)d_in[5];
    float* out = (float*)d_out;

    k_zero<<<2, 256>>>();
    k_hist<<<SCAT_BLOCKS, SCAT_THREADS>>>(lrix);
    k_scan<<<1, 512>>>();
    k_scatter<<<SCAT_BLOCKS, SCAT_THREADS>>>(lrix);
    k_prep<<<NR_OI, 32>>>(roi, hemb, wemb);
    k_main<<<dim3(NR_OI, 8), 128>>>(x, delta, out);
}

// round 5
// speedup vs baseline: 1.0224x; 1.0224x over previous
#include <cuda_runtime.h>
#include <math.h>

#define NP 262144
#define NR_OI 500
#define SUMH 224
#define SUMW 221
#define SCAT_BLOCKS 128
#define SCAT_THREADS 256
#define CHUNK (NP / SCAT_BLOCKS)   // 2048
#define LOG2E 1.4426950408889634f

// ---------------- device scratch (no allocations allowed) ----------------
__device__ int   g_bc[SCAT_BLOCKS][512];   // per-block counts -> bases
__device__ int   g_offsets[NR_OI + 1];
__device__ int   g_perm[NP];
__device__ float g_lc[NR_OI][SUMH];     // LOG2E*emb + log2(cw)   (-inf at edges)
__device__ float g_lemb[NR_OI][SUMH];   // LOG2E*emb
__device__ float g_cw[NR_OI][SUMH];     // w[k-1] + w[k]
__device__ float g_w[NR_OI][SUMH];      // softmax widths (pad 0)
__device__ float g_binloc[NR_OI][SUMH]; // bin locations

__device__ __forceinline__ float ex2f(float a) {
    float r;
    asm("ex2.approx.ftz.f32 %0, %1;" : "=f"(r) : "f"(a));
    return r;
}

// ---------------- grouping pre-pass (atomic-free global) ----------------
__global__ void __launch_bounds__(SCAT_THREADS)
k_hist(const int* __restrict__ lrix) {
    __shared__ int sc[512];
    for (int t = threadIdx.x; t < 512; t += blockDim.x) sc[t] = 0;
    __syncthreads();
    int base = blockIdx.x * CHUNK;
    for (int j = threadIdx.x; j < CHUNK; j += blockDim.x)
        atomicAdd(&sc[lrix[base + j]], 1);
    __syncthreads();
    for (int t = threadIdx.x; t < 512; t += blockDim.x)
        g_bc[blockIdx.x][t] = sc[t];
}

__global__ void __launch_bounds__(512)
k_scan() {
    __shared__ int s[512];
    int t = threadIdx.x;
    int tot = 0;
#pragma unroll 8
    for (int b = 0; b < SCAT_BLOCKS; b++) tot += g_bc[b][t];
    s[t] = tot;
    __syncthreads();
    for (int o = 1; o < 512; o <<= 1) {
        int a = (t >= o) ? s[t - o] : 0;
        __syncthreads();
        s[t] += a;
        __syncthreads();
    }
    int excl = s[t] - tot;
    if (t < NR_OI) g_offsets[t] = excl;
    if (t == NR_OI - 1) g_offsets[NR_OI] = s[t];
    // rewrite g_bc as per-(block,region) bases
    int base = excl;
#pragma unroll 4
    for (int b = 0; b < SCAT_BLOCKS; b++) {
        int v = g_bc[b][t];
        g_bc[b][t] = base;
        base += v;
    }
}

__global__ void __launch_bounds__(SCAT_THREADS)
k_scatter(const int* __restrict__ lrix) {
    __shared__ int sb[512];
    __shared__ int sc[512];
    for (int t = threadIdx.x; t < 512; t += blockDim.x) {
        sb[t] = g_bc[blockIdx.x][t];
        sc[t] = 0;
    }
    __syncthreads();
    int base = blockIdx.x * CHUNK;
    for (int j = threadIdx.x; j < CHUNK; j += blockDim.x) {
        int i = base + j;
        int r = lrix[i];
        int rank = atomicAdd(&sc[r], 1);
        g_perm[sb[r] + rank] = i;
    }
}

// ---------------- per-region table prep ----------------
__device__ __forceinline__ float warp_max(float v) {
#pragma unroll
    for (int o = 16; o; o >>= 1) v = fmaxf(v, __shfl_xor_sync(0xffffffffu, v, o));
    return v;
}
__device__ __forceinline__ float warp_sum(float v) {
#pragma unroll
    for (int o = 16; o; o >>= 1) v += __shfl_xor_sync(0xffffffffu, v, o);
    return v;
}

template <int N, int OH, int OW>
__device__ __forceinline__ void prep_level(int r, int rid,
                                           const float* __restrict__ hemb,
                                           const float* __restrict__ wemb,
                                           float* sw) {
    const int M = N - 1;
    int lane = threadIdx.x;

    float vals[4];
    float mx = -1e30f;
#pragma unroll
    for (int j = 0; j < 4; j++) {
        int k = lane + 32 * j;
        vals[j] = (k < M) ? wemb[(size_t)rid * SUMW + OW + k] : -1e30f;
        mx = fmaxf(mx, vals[j]);
    }
    mx = warp_max(mx);

    float es[4];
    float sum = 0.f;
#pragma unroll
    for (int j = 0; j < 4; j++) {
        int k = lane + 32 * j;
        es[j] = (k < M) ? __expf(vals[j] - mx) : 0.f;
        sum += es[j];
    }
    sum = warp_sum(sum);
    float inv = 1.f / sum;

#pragma unroll
    for (int j = 0; j < 4; j++) {
        int k = lane + 32 * j;
        if (k < M) sw[k] = es[j] * inv;
        else if (k < N) sw[k] = 0.f;
    }
    __syncwarp();

#pragma unroll
    for (int j = 0; j < 4; j++) {
        int k = lane + 32 * j;
        if (k < N) {
            float wk = sw[k];
            float wkm1 = (k > 0) ? sw[k - 1] : 0.f;
            float cw = wk + wkm1;
            float le = LOG2E * hemb[(size_t)rid * SUMH + OH + k];
            g_w[r][OH + k] = wk;
            g_cw[r][OH + k] = cw;
            g_lemb[r][OH + k] = le;
            g_lc[r][OH + k] = (cw > 0.f) ? (le + __log2f(cw)) : -INFINITY;
        }
    }

    // parallel cumsum for bin locations
    {
        const int E = N / 32;
        float loc[E > 0 ? E : 1];
        float s = 0.f;
#pragma unroll
        for (int m = 0; m < E; m++) {
            loc[m] = s;
            s += sw[E * lane + m];
        }
        float run = s;
#pragma unroll
        for (int o = 1; o < 32; o <<= 1) {
            float nv = __shfl_up_sync(0xffffffffu, run, o);
            if (lane >= o) run += nv;
        }
        float excl = run - s;
#pragma unroll
        for (int m = 0; m < E; m++) {
            int k = E * lane + m;
            float bl = excl + loc[m];
            g_binloc[r][OH + k] = (k == 0) ? 0.f : ((k == N - 1) ? 1.f : bl);
        }
    }
    __syncwarp();
}

__global__ void k_prep(const int* __restrict__ roi,
                       const float* __restrict__ hemb,
                       const float* __restrict__ wemb) {
    __shared__ float sw[128];
    int r = blockIdx.x;
    int rid = roi[r];
    prep_level<128, 0, 0>(r, rid, hemb, wemb, sw);
    prep_level<64, 128, 127>(r, rid, hemb, wemb, sw);
    prep_level<32, 192, 190>(r, rid, hemb, wemb, sw);
}

// ---------------- main per-point kernel ----------------
// 8 lanes per point, 4 points per warp; warp-uniform trip counts.

template <int N, int OFF, int NV>
__device__ __forceinline__ void level_eval(float& xv, float& P, int g, int gsh,
                                           const float4* dv,
                                           const float* __restrict__ sLC,
                                           const float* __restrict__ sLE,
                                           const float* __restrict__ sCW,
                                           const float* __restrict__ sW,
                                           const float* __restrict__ sB,
                                           const float* __restrict__ drow) {
    const float* B = sB + OFF;
    const float* LC = sLC + OFF;

    // radix-8 cooperative search: pos = #{k in [1,N-1]: B[k] < xv}
    int pos;
    {
        int step = N / 8;
        int idx = (g + 1) * step;
        if (idx > N - 1) idx = N - 1;
        unsigned b = __ballot_sync(0xffffffffu, B[idx] < xv);
        pos = __popc((b >> gsh) & 0xffu) * step;
    }
    if (N == 128) {
        int idx = pos + (g + 1) * 2;
        if (idx > 127) idx = 127;
        unsigned b = __ballot_sync(0xffffffffu, B[idx] < xv);
        pos += __popc((b >> gsh) & 0xffu) * 2;
        int i2 = pos + 1;
        if (i2 > 127) i2 = 127;
        pos += (B[i2] < xv) ? 1 : 0;
    } else if (N == 64) {
        int idx = pos + (g + 1);
        if (idx > 63) idx = 63;
        unsigned b = __ballot_sync(0xffffffffu, B[idx] < xv);
        pos += __popc((b >> gsh) & 0xffu);
    } else {
        int idx = pos + (g + 1);
        if (idx > 31) idx = 31;
        unsigned b = __ballot_sync(0xffffffffu, B[idx] < xv);
        pos += __popc((b >> gsh) & 0x7u);
    }
    int bin = pos > N - 2 ? N - 2 : pos;

    // fused exp/total/partial pass over preloaded delta
    float tot = 0.f, part = 0.f;
#pragma unroll
    for (int i = 0; i < NV; i++) {
        float dd[4] = {dv[i].x, dv[i].y, dv[i].z, dv[i].w};
#pragma unroll
        for (int jj = 0; jj < 4; jj++) {
            int k = g * 4 + 32 * i + jj;
            float t = ex2f(fmaf(dd[jj], LOG2E, LC[k]));
            tot += t;
            part += (k < bin) ? t : 0.f;
        }
    }
#pragma unroll
    for (int o = 4; o; o >>= 1) {
        tot += __shfl_xor_sync(0xffffffffu, tot, o);
        part += __shfl_xor_sync(0xffffffffu, part, o);
    }

    // epilogue
    float hl = ex2f(fmaf(__ldg(&drow[OFF + bin]), LOG2E, sLE[OFF + bin]));
    float hr = ex2f(fmaf(__ldg(&drow[OFF + bin + 1]), LOG2E, sLE[OFF + bin + 1]));
    float wb = sW[OFF + bin];
    float wbm1 = sCW[OFF + bin] - wb;
    part = fmaf(hl, wbm1, part);

    float inv_t = __fdividef(1.f, tot);
    float Hl = 2.f * hl * inv_t;
    float dh = 2.f * (hr - hl) * inv_t;
    float alpha = (xv - B[bin]) * __fdividef(1.f, wb);
    xv = (0.5f * dh * alpha + Hl) * (wb * alpha) + part * inv_t;
    P *= fmaf(alpha, dh, Hl);
}

__global__ void __launch_bounds__(128)
k_main(const float* __restrict__ x,
       const float* __restrict__ delta,
       float* __restrict__ out) {
    __shared__ float sLC[SUMH];
    __shared__ float sLE[SUMH];
    __shared__ float sCW[SUMH];
    __shared__ float sW[SUMH];
    __shared__ float sB[SUMH];

    int r = blockIdx.x;
    for (int i = threadIdx.x; i < SUMH; i += blockDim.x) {
        sLC[i] = g_lc[r][i];
        sLE[i] = g_lemb[r][i];
        sCW[i] = g_cw[r][i];
        sW[i] = g_w[r][i];
        sB[i] = g_binloc[r][i];
    }
    __syncthreads();

    int g = threadIdx.x & 7;
    int gsh = (threadIdx.x & 31) & 24;   // group bit-offset within warp ballot
    int grpInBlock = threadIdx.x >> 3;   // 0..15
    int beg = g_offsets[r];
    int end = g_offsets[r + 1];
    int stride = gridDim.y * 16;

    for (int j0 = beg + blockIdx.y * 16; j0 < end; j0 += stride) {
        int j = j0 + grpInBlock;
        bool valid = j < end;
        int jc = valid ? j : end - 1;
        int p = g_perm[jc];
        float xv = __ldg(&x[p]);
        float P = 1.f;
        const float* drow = delta + (size_t)p * SUMH;
        const float4* d4 = reinterpret_cast<const float4*>(drow);

        // preload all delta for this point (7 LDG.128 in flight per lane)
        float4 dv[7];
#pragma unroll
        for (int i = 0; i < 4; i++) dv[i] = __ldg(&d4[g + 8 * i]);
        dv[4] = __ldg(&d4[32 + g]);
        dv[5] = __ldg(&d4[40 + g]);
        dv[6] = __ldg(&d4[48 + g]);

        level_eval<128, 0, 4>(xv, P, g, gsh, dv, sLC, sLE, sCW, sW, sB, drow);
        level_eval<64, 128, 2>(xv, P, g, gsh, dv + 4, sLC, sLE, sCW, sW, sB, drow);
        level_eval<32, 192, 1>(xv, P, g, gsh, dv + 6, sLC, sLE, sCW, sW, sB, drow);

        if (valid && g == 0) {
            out[p] = xv;
            out[NP + p] = __logf(P);
        }
    }
}

// ---------------- launch ----------------
extern "C" void kernel_launch(void* const* d_in, const int* in_sizes, int n_in,
                              void* d_out, int out_size) {
    const float* x     = (const float*)d_in[0];
    const int*   roi   = (const int*)d_in[1];
    const int*   lrix  = (const int*)d_in[2];
    const float* delta = (const float*)d_in[3];
    const float* hemb  = (const float*)d_in[4];
    const float* wemb  = (const float*)d_in[5];
    float* out = (float*)d_out;

    k_hist<<<SCAT_BLOCKS, SCAT_THREADS>>>(lrix);
    k_scan<<<1, 512>>>();
    k_scatter<<<SCAT_BLOCKS, SCAT_THREADS>>>(lrix);
    k_prep<<<NR_OI, 32>>>(roi, hemb, wemb);
    k_main<<<dim3(NR_OI, 8), 128>>>(x, delta, out);
}

// round 6
// speedup vs baseline: 1.0713x; 1.0478x over previous
#include <cuda_runtime.h>
#include <math.h>

#define NP 262144
#define NR_OI 500
#define SUMH 224
#define SUMW 221
#define SCAT_BLOCKS 128
#define SCAT_THREADS 256
#define CHUNK (NP / SCAT_BLOCKS)   // 2048
#define LOG2E 1.4426950408889634f

// ---------------- device scratch (no allocations allowed) ----------------
__device__ int            g_bc[SCAT_BLOCKS][512];  // per-block counts -> bases
__device__ int            g_offsets[NR_OI + 1];
__device__ unsigned short g_rank[NP];
__device__ int            g_perm[NP];

__device__ __forceinline__ float ex2f(float a) {
    float r;
    asm("ex2.approx.ftz.f32 %0, %1;" : "=f"(r) : "f"(a));
    return r;
}

// ---------------- grouping pre-pass (atomic-free global) ----------------
__global__ void __launch_bounds__(SCAT_THREADS)
k_hist(const int* __restrict__ lrix) {
    __shared__ int sc[512];
    for (int t = threadIdx.x; t < 512; t += blockDim.x) sc[t] = 0;
    __syncthreads();
    int base = blockIdx.x * CHUNK;
    for (int j = threadIdx.x; j < CHUNK; j += blockDim.x) {
        int i = base + j;
        int rank = atomicAdd(&sc[lrix[i]], 1);
        g_rank[i] = (unsigned short)rank;
    }
    __syncthreads();
    for (int t = threadIdx.x; t < 512; t += blockDim.x)
        g_bc[blockIdx.x][t] = sc[t];
}

__global__ void __launch_bounds__(512)
k_scan() {
    __shared__ int s[512];
    int t = threadIdx.x;
    int tot = 0;
#pragma unroll 8
    for (int b = 0; b < SCAT_BLOCKS; b++) tot += g_bc[b][t];
    s[t] = tot;
    __syncthreads();
    for (int o = 1; o < 512; o <<= 1) {
        int a = (t >= o) ? s[t - o] : 0;
        __syncthreads();
        s[t] += a;
        __syncthreads();
    }
    int excl = s[t] - tot;
    if (t < NR_OI) g_offsets[t] = excl;
    if (t == NR_OI - 1) g_offsets[NR_OI] = s[t];
    int base = excl;
#pragma unroll 4
    for (int b = 0; b < SCAT_BLOCKS; b++) {
        int v = g_bc[b][t];
        g_bc[b][t] = base;
        base += v;
    }
}

__global__ void __launch_bounds__(SCAT_THREADS)
k_scatter(const int* __restrict__ lrix) {
    __shared__ int sb[512];
    for (int t = threadIdx.x; t < 512; t += blockDim.x)
        sb[t] = g_bc[blockIdx.x][t];
    __syncthreads();
    int base = blockIdx.x * CHUNK;
    for (int j = threadIdx.x; j < CHUNK; j += blockDim.x) {
        int i = base + j;
        g_perm[sb[lrix[i]] + (int)g_rank[i]] = i;
    }
}

// ---------------- in-kernel per-region table prep (one warp per level) ----
__device__ __forceinline__ float warp_max(float v) {
#pragma unroll
    for (int o = 16; o; o >>= 1) v = fmaxf(v, __shfl_xor_sync(0xffffffffu, v, o));
    return v;
}
__device__ __forceinline__ float warp_sum(float v) {
#pragma unroll
    for (int o = 16; o; o >>= 1) v += __shfl_xor_sync(0xffffffffu, v, o);
    return v;
}

template <int N, int OH, int OW>
__device__ __forceinline__ void prep_level_w(int lane, int rid,
                                             const float* __restrict__ hemb,
                                             const float* __restrict__ wemb,
                                             float* sLC, float* sLE,
                                             float* sCW, float* sW, float* sB) {
    const int M = N - 1;
    const int J = N / 32;

    float vals[J];
    float mx = -1e30f;
#pragma unroll
    for (int j = 0; j < J; j++) {
        int k = lane + 32 * j;
        vals[j] = (k < M) ? __ldg(&wemb[(size_t)rid * SUMW + OW + k]) : -1e30f;
        mx = fmaxf(mx, vals[j]);
    }
    mx = warp_max(mx);

    float es[J];
    float sum = 0.f;
#pragma unroll
    for (int j = 0; j < J; j++) {
        int k = lane + 32 * j;
        es[j] = (k < M) ? __expf(vals[j] - mx) : 0.f;
        sum += es[j];
    }
    sum = warp_sum(sum);
    float inv = 1.f / sum;

#pragma unroll
    for (int j = 0; j < J; j++) {
        int k = lane + 32 * j;
        sW[OH + k] = (k < M) ? es[j] * inv : 0.f;
    }
    __syncwarp();

#pragma unroll
    for (int j = 0; j < J; j++) {
        int k = lane + 32 * j;
        float wk = sW[OH + k];
        float wkm1 = (k > 0) ? sW[OH + k - 1] : 0.f;
        float cw = wk + wkm1;
        float le = LOG2E * __ldg(&hemb[(size_t)rid * SUMH + OH + k]);
        sCW[OH + k] = cw;
        sLE[OH + k] = le;
        sLC[OH + k] = le + __log2f(cw);
    }
    __syncwarp();

    // bin locations: per-lane serial over E contiguous, warp scan across lanes
    {
        const int E = N / 32;
        float loc[E];
        float s = 0.f;
#pragma unroll
        for (int m = 0; m < E; m++) {
            loc[m] = s;
            s += sW[OH + E * lane + m];
        }
        float run = s;
#pragma unroll
        for (int o = 1; o < 32; o <<= 1) {
            float nv = __shfl_up_sync(0xffffffffu, run, o);
            if (lane >= o) run += nv;
        }
        float excl = run - s;
#pragma unroll
        for (int m = 0; m < E; m++) {
            int k = E * lane + m;
            sB[OH + k] = (k == 0) ? 0.f : ((k == N - 1) ? 1.f : excl + loc[m]);
        }
    }
}

// ---------------- main per-point kernel ----------------
template <int N, int OFF, int NV>
__device__ __forceinline__ void level_eval(float& xv, float& P, int g, int gsh,
                                           const float4* dv,
                                           const float* __restrict__ sLC,
                                           const float* __restrict__ sLE,
                                           const float* __restrict__ sCW,
                                           const float* __restrict__ sW,
                                           const float* __restrict__ sB,
                                           const float* __restrict__ drow) {
    const float* B = sB + OFF;
    const float* LC = sLC + OFF;

    // radix-8 cooperative search: pos = #{k in [1,N-1]: B[k] < xv}
    int pos;
    {
        int step = N / 8;
        int idx = (g + 1) * step;
        if (idx > N - 1) idx = N - 1;
        unsigned b = __ballot_sync(0xffffffffu, B[idx] < xv);
        pos = __popc((b >> gsh) & 0xffu) * step;
    }
    if (N == 128) {
        int idx = pos + (g + 1) * 2;
        if (idx > 127) idx = 127;
        unsigned b = __ballot_sync(0xffffffffu, B[idx] < xv);
        pos += __popc((b >> gsh) & 0xffu) * 2;
        int i2 = pos + 1;
        if (i2 > 127) i2 = 127;
        pos += (B[i2] < xv) ? 1 : 0;
    } else if (N == 64) {
        int idx = pos + (g + 1);
        if (idx > 63) idx = 63;
        unsigned b = __ballot_sync(0xffffffffu, B[idx] < xv);
        pos += __popc((b >> gsh) & 0xffu);
    } else {
        int idx = pos + (g + 1);
        if (idx > 31) idx = 31;
        unsigned b = __ballot_sync(0xffffffffu, B[idx] < xv);
        pos += __popc((b >> gsh) & 0x7u);
    }
    int bin = pos > N - 2 ? N - 2 : pos;

    float tot = 0.f, part = 0.f;
#pragma unroll
    for (int i = 0; i < NV; i++) {
        float dd[4] = {dv[i].x, dv[i].y, dv[i].z, dv[i].w};
#pragma unroll
        for (int jj = 0; jj < 4; jj++) {
            int k = g * 4 + 32 * i + jj;
            float t = ex2f(fmaf(dd[jj], LOG2E, LC[k]));
            tot += t;
            part += (k < bin) ? t : 0.f;
        }
    }
#pragma unroll
    for (int o = 4; o; o >>= 1) {
        tot += __shfl_xor_sync(0xffffffffu, tot, o);
        part += __shfl_xor_sync(0xffffffffu, part, o);
    }

    float hl = ex2f(fmaf(__ldg(&drow[OFF + bin]), LOG2E, sLE[OFF + bin]));
    float hr = ex2f(fmaf(__ldg(&drow[OFF + bin + 1]), LOG2E, sLE[OFF + bin + 1]));
    float wb = sW[OFF + bin];
    float wbm1 = sCW[OFF + bin] - wb;
    part = fmaf(hl, wbm1, part);

    float inv_t = __fdividef(1.f, tot);
    float Hl = 2.f * hl * inv_t;
    float dh = 2.f * (hr - hl) * inv_t;
    float alpha = (xv - B[bin]) * __fdividef(1.f, wb);
    xv = (0.5f * dh * alpha + Hl) * (wb * alpha) + part * inv_t;
    P *= fmaf(alpha, dh, Hl);
}

__global__ void __launch_bounds__(128)
k_main(const float* __restrict__ x,
       const float* __restrict__ delta,
       const int* __restrict__ roi,
       const float* __restrict__ hemb,
       const float* __restrict__ wemb,
       float* __restrict__ out) {
    __shared__ float sLC[SUMH];
    __shared__ float sLE[SUMH];
    __shared__ float sCW[SUMH];
    __shared__ float sW[SUMH];
    __shared__ float sB[SUMH];

    int r = blockIdx.x;
    {
        int warp = threadIdx.x >> 5;
        int lane = threadIdx.x & 31;
        int rid = __ldg(&roi[r]);
        if (warp == 0)
            prep_level_w<128, 0, 0>(lane, rid, hemb, wemb, sLC, sLE, sCW, sW, sB);
        else if (warp == 1)
            prep_level_w<64, 128, 127>(lane, rid, hemb, wemb, sLC, sLE, sCW, sW, sB);
        else if (warp == 2)
            prep_level_w<32, 192, 190>(lane, rid, hemb, wemb, sLC, sLE, sCW, sW, sB);
    }
    __syncthreads();

    int g = threadIdx.x & 7;
    int gsh = (threadIdx.x & 31) & 24;
    int grpInBlock = threadIdx.x >> 3;
    int beg = g_offsets[r];
    int end = g_offsets[r + 1];
    int stride = gridDim.y * 16;

    for (int j0 = beg + blockIdx.y * 16; j0 < end; j0 += stride) {
        int j = j0 + grpInBlock;
        bool valid = j < end;
        int jc = valid ? j : end - 1;
        int p = g_perm[jc];
        float xv = __ldg(&x[p]);
        float P = 1.f;
        const float* drow = delta + (size_t)p * SUMH;
        const float4* d4 = reinterpret_cast<const float4*>(drow);

        float4 dv[7];
#pragma unroll
        for (int i = 0; i < 4; i++) dv[i] = __ldg(&d4[g + 8 * i]);
        dv[4] = __ldg(&d4[32 + g]);
        dv[5] = __ldg(&d4[40 + g]);
        dv[6] = __ldg(&d4[48 + g]);

        level_eval<128, 0, 4>(xv, P, g, gsh, dv, sLC, sLE, sCW, sW, sB, drow);
        level_eval<64, 128, 2>(xv, P, g, gsh, dv + 4, sLC, sLE, sCW, sW, sB, drow);
        level_eval<32, 192, 1>(xv, P, g, gsh, dv + 6, sLC, sLE, sCW, sW, sB, drow);

        if (valid && g == 0) {
            out[p] = xv;
            out[NP + p] = __logf(P);
        }
    }
}

// ---------------- launch ----------------
extern "C" void kernel_launch(void* const* d_in, const int* in_sizes, int n_in,
                              void* d_out, int out_size) {
    const float* x     = (const float*)d_in[0];
    const int*   roi   = (const int*)d_in[1];
    const int*   lrix  = (const int*)d_in[2];
    const float* delta = (const float*)d_in[3];
    const float* hemb  = (const float*)d_in[4];
    const float* wemb  = (const float*)d_in[5];
    float* out = (float*)d_out;

    k_hist<<<SCAT_BLOCKS, SCAT_THREADS>>>(lrix);
    k_scan<<<1, 512>>>();
    k_scatter<<<SCAT_BLOCKS, SCAT_THREADS>>>(lrix);
    k_main<<<dim3(NR_OI, 8), 128>>>(x, delta, roi, hemb, wemb, out);
}